// round 13
// baseline (speedup 1.0000x reference)
#include <cuda_runtime.h>
#include <math.h>

#define BQ 8
#define TQ 96
#define NQ 20000
#define PQ 12
#define LQ 3
#define DQ 32
#define CQ 128
#define MQ 64

// ---------------- scratch (static device globals; no allocation) ----------------
__device__ float g_h   [BQ*NQ*CQ];   // evolving hidden state
__device__ float g_h0  [BQ*NQ*CQ];   // skip copy
__device__ float g_phiq[BQ*NQ*MQ];   // phi_q (later scaled by 1/den)
__device__ float g_phik[BQ*NQ*MQ];   // pass1: dash_k - diag_k ; pass2: phi_k
__device__ float g_A1  [NQ*DQ];
__device__ float g_A2  [NQ*DQ];
__device__ float g_kv  [BQ*MQ*CQ];
__device__ float g_ksum[BQ*MQ];
__device__ unsigned int g_kmax[BQ];
__device__ float g_T1[BQ*DQ], g_T2[BQ*DQ], g_bias2[BQ*DQ];
__device__ float g_te[BQ*DQ], g_we[BQ*DQ];

// ---------------- helpers ----------------
union F2U { float2 f; unsigned long long u; };
__device__ __forceinline__ float2 ffma2(float2 a, float2 b, float2 c) {
    F2U A, Bv, Cv, Dv; A.f = a; Bv.f = b; Cv.f = c;
    asm("fma.rn.f32x2 %0, %1, %2, %3;" : "=l"(Dv.u) : "l"(A.u), "l"(Bv.u), "l"(Cv.u));
    return Dv.f;
}
__device__ __forceinline__ float2 fdup(float x) { return make_float2(x, x); }

__device__ __forceinline__ unsigned fkey(float f) {
    unsigned u = __float_as_uint(f);
    return (u & 0x80000000u) ? ~u : (u | 0x80000000u);
}
__device__ __forceinline__ float fdec(unsigned k) {
    unsigned u = (k & 0x80000000u) ? (k ^ 0x80000000u) : ~k;
    return __uint_as_float(u);
}

#define SCALE_RF 0.4204482076268573f   /* 32^(-1/4) */
#define RATIO_RF 0.125f                /* 1/sqrt(64) */
#define EPS_RF   1e-6f
#define IST      2.0f                  /* 1/sqrt(tau), tau=0.25 */

// ---------------- K0: per-batch precompute ----------------
__global__ void k_prep(const float* __restrict__ x_mark,
                       const float* __restrict__ time_tab,
                       const float* __restrict__ week_tab,
                       const float* __restrict__ input_w,
                       const float* __restrict__ input_b,
                       const float* __restrict__ w1_w, const float* __restrict__ w1_b,
                       const float* __restrict__ w2_w, const float* __restrict__ w2_b) {
    int b = blockIdx.x, t = threadIdx.x;
    __shared__ float m0[TQ], m1[TQ];
    __shared__ int s_tod, s_dow;
    if (t < TQ) { m0[t] = x_mark[(b*TQ + t)*2 + 0]; m1[t] = x_mark[(b*TQ + t)*2 + 1]; }
    __syncthreads();
    if (t == 0) {
        int tod = (int)(m0[TQ-1] * (float)TQ); tod = min(max(tod, 0), TQ-1);
        int dow = (int)(m1[TQ-1] * 7.0f);      dow = min(max(dow, 0), 6);
        s_tod = tod; s_dow = dow;
    }
    __syncthreads();
    if (t < DQ) {
        int c = t;
        float a1 = w1_b[c], a2 = w2_b[c];
        #pragma unroll
        for (int g = 0; g < DQ; g++) {
            float te = time_tab[s_tod*DQ + g], we = week_tab[s_dow*DQ + g];
            a1 += te * w1_w[c*96 + 32 + g] + we * w1_w[c*96 + 64 + g];
            a2 += te * w2_w[c*96 + 32 + g] + we * w2_w[c*96 + 64 + g];
        }
        g_T1[b*DQ + c] = IST * a1;
        g_T2[b*DQ + c] = IST * a2;
        float bb = input_b[c];
        for (int tt = 0; tt < TQ; tt++)
            bb += m0[tt] * input_w[c*288 + 96 + tt] + m1[tt] * input_w[c*288 + 192 + tt];
        g_bias2[b*DQ + c] = bb;
        g_te[b*DQ + c] = time_tab[s_tod*DQ + c];
        g_we[b*DQ + c] = week_tab[s_dow*DQ + c];
    }
    if (t < MQ) g_ksum[b*MQ + t] = 0.0f;
    if (t == 0) g_kmax[b] = 0u;
}

// ---------------- K1: A1/A2 node matrices ----------------
__global__ void k_nodeA(const float* __restrict__ node_emb,
                        const float* __restrict__ w1_w,
                        const float* __restrict__ w2_w) {
    __shared__ float w1s[32*33], w2s[32*33], ne[8*33];
    int t = threadIdx.x;
    for (int i = 0; i < 4; i++) {
        int idx = i*256 + t; int c = idx >> 5, g = idx & 31;
        w1s[c*33 + g] = w1_w[c*96 + g];
        w2s[c*33 + g] = w2_w[c*96 + g];
    }
    {
        int row = t >> 5, g = t & 31;
        ne[row*33 + g] = node_emb[(blockIdx.x*8 + row)*DQ + g];
    }
    __syncthreads();
    int row = t >> 5, c = t & 31;
    int n = blockIdx.x*8 + row;
    float a1 = 0.f, a2 = 0.f;
    #pragma unroll
    for (int g = 0; g < 32; g++) {
        float nv = ne[row*33 + g];
        a1 += nv * w1s[c*33 + g];
        a2 += nv * w2s[c*33 + g];
    }
    g_A1[n*DQ + c] = IST * a1;
    g_A2[n*DQ + c] = IST * a2;
}

// ---------------- K2: input embedding + build h/h0 ----------------
__global__ void k_embed(const float* __restrict__ x,
                        const float* __restrict__ input_w,
                        const float* __restrict__ node_emb) {
    __shared__ float ws[TQ*36];
    int t = threadIdx.x, b = blockIdx.y;
    for (int i = 0; i < 12; i++) {
        int idx = i*256 + t;
        if (idx < TQ*DQ) {
            int c = idx / TQ, tt = idx % TQ;
            ws[tt*36 + c] = input_w[c*288 + tt];
        }
    }
    __syncthreads();
    int n = blockIdx.x*256 + t;
    if (n >= NQ) return;
    float acc[32];
    #pragma unroll
    for (int c = 0; c < 32; c++) acc[c] = 0.f;
    for (int tt = 0; tt < TQ; tt++) {
        float xv = x[(b*TQ + tt)*NQ + n];
        const float4* wrow = (const float4*)&ws[tt*36];
        #pragma unroll
        for (int c4 = 0; c4 < 8; c4++) {
            float4 w = wrow[c4];
            acc[4*c4+0] += xv * w.x; acc[4*c4+1] += xv * w.y;
            acc[4*c4+2] += xv * w.z; acc[4*c4+3] += xv * w.w;
        }
    }
    int base = (b*NQ + n)*CQ;
    const float4* b4  = (const float4*)&g_bias2[b*DQ];
    const float4* te4 = (const float4*)&g_te[b*DQ];
    const float4* we4 = (const float4*)&g_we[b*DQ];
    const float4* ne4 = (const float4*)&node_emb[n*DQ];
    #pragma unroll
    for (int c4 = 0; c4 < 8; c4++) {
        float4 bb = b4[c4];
        float4 v = make_float4(acc[4*c4+0]+bb.x, acc[4*c4+1]+bb.y,
                               acc[4*c4+2]+bb.z, acc[4*c4+3]+bb.w);
        ((float4*)&g_h [base])[c4] = v;  ((float4*)&g_h0[base])[c4] = v;
        float4 nv = ne4[c4];
        ((float4*)&g_h [base+32])[c4] = nv; ((float4*)&g_h0[base+32])[c4] = nv;
        float4 tv = te4[c4];
        ((float4*)&g_h [base+64])[c4] = tv; ((float4*)&g_h0[base+64])[c4] = tv;
        float4 wv = we4[c4];
        ((float4*)&g_h [base+96])[c4] = wv; ((float4*)&g_h0[base+96])[c4] = wv;
    }
}

// ---------------- K3: phi pass 1 ----------------
// phi_q finalized (per-row stabilizer); phi_k stored as dash_k - diag_k; per-b max(dash_k) atomically.
__global__ void k_phi1(const float* __restrict__ proj) {
    __shared__ float proj_s[MQ*33];
    __shared__ float nv1_s[32*33], nv2_s[32*33];
    __shared__ float diag1[32], diag2[32];
    __shared__ unsigned s_bmax;
    int t = threadIdx.x, b = blockIdx.y;
    int n0 = blockIdx.x * 32;
    if (t == 0) s_bmax = 0u;
    for (int i = 0; i < 8; i++) {
        int idx = i*256 + t; int m = idx >> 5, d = idx & 31;
        proj_s[m*33 + d] = proj[m*32 + d];
    }
    for (int i = 0; i < 4; i++) {
        int idx = i*256 + t; int r = idx >> 5, d = idx & 31;
        float tv1 = g_T1[b*DQ + d], tv2 = g_T2[b*DQ + d];
        nv1_s[r*33 + d] = g_A1[(n0 + r)*DQ + d] + tv1;
        nv2_s[r*33 + d] = g_A2[(n0 + r)*DQ + d] + tv2;
    }
    __syncthreads();
    if (t < 64) {
        int r = t & 31;
        const float* src = (t < 32) ? &nv1_s[r*33] : &nv2_s[r*33];
        float s = 0.f;
        #pragma unroll
        for (int d = 0; d < 32; d++) { float v = src[d]; s += v*v; }
        float dg = 0.5f * SCALE_RF * SCALE_RF * s;
        if (t < 32) diag1[r] = dg; else diag2[r] = dg;
    }
    __syncthreads();

    int r = t >> 3, j = t & 7;
    int n = n0 + r;
    int base = (b*NQ + n)*MQ;

    // ---- query ----
    {
        float nvr[32];
        #pragma unroll
        for (int d = 0; d < 32; d++) nvr[d] = nv1_s[r*33 + d];
        float dq[8];
        #pragma unroll
        for (int k = 0; k < 8; k++) {
            int m = j + 8*k;
            float s = 0.f;
            #pragma unroll
            for (int d = 0; d < 32; d++) s += nvr[d] * proj_s[m*33 + d];
            dq[k] = s * SCALE_RF;
        }
        float mx = dq[0];
        #pragma unroll
        for (int k = 1; k < 8; k++) mx = fmaxf(mx, dq[k]);
        #pragma unroll
        for (int off = 1; off < 8; off <<= 1)
            mx = fmaxf(mx, __shfl_xor_sync(0xffffffffu, mx, off));
        float dg = diag1[r];
        #pragma unroll
        for (int k = 0; k < 8; k++)
            g_phiq[base + j + 8*k] = RATIO_RF * (__expf(dq[k] - dg - mx) + EPS_RF);
    }
    // ---- key ----
    {
        float nvr[32];
        #pragma unroll
        for (int d = 0; d < 32; d++) nvr[d] = nv2_s[r*33 + d];
        float mxk = -1e30f;
        float dg = diag2[r];
        #pragma unroll
        for (int k = 0; k < 8; k++) {
            int m = j + 8*k;
            float s = 0.f;
            #pragma unroll
            for (int d = 0; d < 32; d++) s += nvr[d] * proj_s[m*33 + d];
            float dk = s * SCALE_RF;
            mxk = fmaxf(mxk, dk);
            g_phik[base + m] = dk - dg;
        }
        #pragma unroll
        for (int off = 1; off < 32; off <<= 1)
            mxk = fmaxf(mxk, __shfl_xor_sync(0xffffffffu, mxk, off));
        if ((t & 31) == 0) atomicMax(&s_bmax, fkey(mxk));
    }
    __syncthreads();
    if (t == 0) atomicMax(&g_kmax[b], s_bmax);
}

// ---------------- K4: phi_k finalize + ksum ----------------
__global__ void k_phi2() {
    __shared__ float red[4][MQ];
    int t = threadIdx.x, b = blockIdx.y;
    int m = t & 63, g = t >> 6;
    float kmaxf = fdec(g_kmax[b]);
    int n0 = blockIdx.x * 500;
    float s = 0.f;
    for (int n = n0 + g; n < n0 + 500; n += 4) {
        int idx = (b*NQ + n)*MQ + m;
        float v = RATIO_RF * (__expf(g_phik[idx] - kmaxf) + EPS_RF);
        g_phik[idx] = v;
        s += v;
    }
    red[g][m] = s;
    __syncthreads();
    if (t < MQ) {
        float tot = red[0][t] + red[1][t] + red[2][t] + red[3][t];
        atomicAdd(&g_ksum[b*MQ + t], tot);
    }
}

// ---------------- K5: fold 1/den into phi_q ----------------
__global__ void k_den() {
    __shared__ float ks[MQ];
    int t = threadIdx.x, b = blockIdx.y;
    if (t < MQ) ks[t] = g_ksum[b*MQ + t];
    __syncthreads();
    int w = t >> 5, l = t & 31;
    int n = blockIdx.x*8 + w;
    int base = (b*NQ + n)*MQ;
    float v0 = g_phiq[base + l], v1 = g_phiq[base + 32 + l];
    float p = v0 * ks[l] + v1 * ks[32 + l];
    #pragma unroll
    for (int off = 1; off < 32; off <<= 1)
        p += __shfl_xor_sync(0xffffffffu, p, off);
    float inv = 1.0f / p;
    g_phiq[base + l] = v0 * inv;
    g_phiq[base + 32 + l] = v1 * inv;
}

// ---------------- K6: zero kv ----------------
__global__ void k_zero() {
    int idx = (blockIdx.x*256 + threadIdx.x) * 8;
    #pragma unroll
    for (int i = 0; i < 8; i++) g_kv[idx + i] = 0.f;
}

// ---------------- K7: fused gate + kv accumulation ----------------
#define K7_SMEM ((2*128*129 + 128*34 + 32*128 + 32*64) * 4)
__global__ __launch_bounds__(256, 1)
void k_gatekv(int layer,
              const float* __restrict__ in_w,  const float* __restrict__ in_b,
              const float* __restrict__ out_w, const float* __restrict__ out_b) {
    extern __shared__ float sm[];
    float* wgIn  = sm;                       // [128][129] : wgIn[g*129+c]
    float* wgOut = wgIn  + 128*129;
    float* hT    = wgOut + 128*129;          // [128][34]  : hT[c*34+n]
    float* uS    = hT    + 128*34;           // [32][128]
    float* phS   = uS    + 32*128;           // [32][64]

    int t = threadIdx.x, b = blockIdx.y;
    // load transposed weights
    for (int i = 0; i < 64; i++) {
        int flat = i*256 + t;
        int c = flat >> 7, g = flat & 127;
        wgIn [g*129 + c] = in_w [(layer*CQ + c)*CQ + g];
        wgOut[g*129 + c] = out_w[(layer*CQ + c)*CQ + g];
    }
    int c  = t & 127, q = t >> 7;           // phase-1 mapping
    int m0 = t & 31,  cg = t >> 5;          // phase-2 mapping
    int c0 = cg * 16;
    float bIn  = in_b [layer*CQ + c];
    float bOut = out_b[layer*CQ + c];

    float2 kvacc[16];
    #pragma unroll
    for (int i = 0; i < 16; i++) kvacc[i] = make_float2(0.f, 0.f);

    int t0 = blockIdx.x * 35;
    int t1 = min(t0 + 35, NQ/32);
    for (int tile = t0; tile < t1; tile++) {
        int n0 = tile * 32;
        __syncthreads();
        // stage h (transposed) and phi_k
        for (int i = 0; i < 16; i++) {
            int flat = i*256 + t; int n = flat >> 7, cc = flat & 127;
            hT[cc*34 + n] = g_h[(b*NQ + n0 + n)*CQ + cc];
        }
        for (int i = 0; i < 8; i++) {
            int flat = i*256 + t; int n = flat >> 6, m = flat & 63;
            phS[n*MQ + m] = g_phik[(b*NQ + n0 + n)*MQ + m];
        }
        __syncthreads();

        // ---- phase 1: gates (node pairs packed f32x2) ----
        float2 ain[8], aout[8];
        #pragma unroll
        for (int p = 0; p < 8; p++) { ain[p] = fdup(bIn); aout[p] = fdup(bOut); }
        #pragma unroll 4
        for (int g = 0; g < 128; g++) {
            float2 wi = fdup(wgIn [g*129 + c]);
            float2 wo = fdup(wgOut[g*129 + c]);
            const float* hrow = &hT[g*34];
            #pragma unroll
            for (int p = 0; p < 8; p++) {
                int pr = q + 2*p;
                float2 h2 = *(const float2*)&hrow[2*pr];
                ain [p] = ffma2(h2, wi, ain [p]);
                aout[p] = ffma2(h2, wo, aout[p]);
            }
        }
        #pragma unroll
        for (int p = 0; p < 8; p++) {
            int pr = q + 2*p;
            float u0 = (1.f / (1.f + __expf(-ain[p].x))) * aout[p].x;
            float u1 = (1.f / (1.f + __expf(-ain[p].y))) * aout[p].y;
            uS[(2*pr  )*CQ + c] = u0;
            uS[(2*pr+1)*CQ + c] = u1;
        }
        __syncthreads();

        // ---- phase 2: kv += phi_k^T u ----
        #pragma unroll 2
        for (int n = 0; n < 32; n++) {
            float2 pa = fdup(phS[n*MQ + m0]);
            float2 pb = fdup(phS[n*MQ + m0 + 32]);
            const float* urow = &uS[n*CQ + c0];
            #pragma unroll
            for (int j = 0; j < 8; j++) {
                float2 u2 = *(const float2*)&urow[2*j];
                kvacc[j]     = ffma2(pa, u2, kvacc[j]);
                kvacc[8 + j] = ffma2(pb, u2, kvacc[8 + j]);
            }
        }
    }
    // flush kv
    #pragma unroll
    for (int j = 0; j < 8; j++) {
        atomicAdd(&g_kv[(b*MQ + m0     )*CQ + c0 + 2*j    ], kvacc[j].x);
        atomicAdd(&g_kv[(b*MQ + m0     )*CQ + c0 + 2*j + 1], kvacc[j].y);
        atomicAdd(&g_kv[(b*MQ + m0 + 32)*CQ + c0 + 2*j    ], kvacc[8+j].x);
        atomicAdd(&g_kv[(b*MQ + m0 + 32)*CQ + c0 + 2*j + 1], kvacc[8+j].y);
    }
}

// ---------------- K8: apply attention + residual + LayerNorm ----------------
#define K8_SMEM ((64*128 + 64*34 + 32*132) * 4)
__global__ __launch_bounds__(256, 1)
void k_apply(int layer,
             const float* __restrict__ ln_g, const float* __restrict__ ln_b) {
    extern __shared__ float sm[];
    float* kv_s = sm;                 // [64][128]
    float* phiT = kv_s + 64*128;      // [64][34] : phiT[m*34+n]
    float* hout = phiT + 64*34;       // [32][132]

    int t = threadIdx.x, b = blockIdx.y;
    for (int i = 0; i < 32; i++) {
        int idx = i*256 + t;
        kv_s[idx] = g_kv[b*MQ*CQ + idx];
    }
    int c = t & 127, q = t >> 7;
    int warpId = t >> 5, lane = t & 31;
    float4 lg4 = *(const float4*)&ln_g[layer*CQ + 4*lane];
    float4 lb4 = *(const float4*)&ln_b[layer*CQ + 4*lane];

    int t0 = blockIdx.x * 35;
    int t1 = min(t0 + 35, NQ/32);
    for (int tile = t0; tile < t1; tile++) {
        int n0 = tile * 32;
        __syncthreads();
        for (int i = 0; i < 8; i++) {
            int flat = i*256 + t; int n = flat >> 6, m = flat & 63;
            phiT[m*34 + n] = g_phiq[(b*NQ + n0 + n)*MQ + m];
        }
        __syncthreads();

        float2 acc[8];
        #pragma unroll
        for (int p = 0; p < 8; p++) acc[p] = make_float2(0.f, 0.f);
        #pragma unroll 4
        for (int m = 0; m < 64; m++) {
            float2 k2 = fdup(kv_s[m*CQ + c]);
            const float* prow = &phiT[m*34];
            #pragma unroll
            for (int p = 0; p < 8; p++) {
                int pr = q + 2*p;
                float2 ph2 = *(const float2*)&prow[2*pr];
                acc[p] = ffma2(ph2, k2, acc[p]);
            }
        }
        #pragma unroll
        for (int p = 0; p < 8; p++) {
            int pr = q + 2*p;
            int na = 2*pr, nb = 2*pr + 1;
            float r0 = g_h[(b*NQ + n0 + na)*CQ + c];
            float r1 = g_h[(b*NQ + n0 + nb)*CQ + c];
            hout[na*132 + c] = acc[p].x + r0;
            hout[nb*132 + c] = acc[p].y + r1;
        }
        __syncthreads();

        // LayerNorm: warp per node
        for (int rep = 0; rep < 4; rep++) {
            int node = rep*8 + warpId;
            float4 v = *(const float4*)&hout[node*132 + 4*lane];
            float s  = v.x + v.y + v.z + v.w;
            float s2 = v.x*v.x + v.y*v.y + v.z*v.z + v.w*v.w;
            #pragma unroll
            for (int off = 1; off < 32; off <<= 1) {
                s  += __shfl_xor_sync(0xffffffffu, s,  off);
                s2 += __shfl_xor_sync(0xffffffffu, s2, off);
            }
            float mu  = s * (1.0f/128.0f);
            float var = s2 * (1.0f/128.0f) - mu*mu;
            float rstd = rsqrtf(var + 1e-5f);
            float4 o;
            o.x = (v.x - mu)*rstd*lg4.x + lb4.x;
            o.y = (v.y - mu)*rstd*lg4.y + lb4.y;
            o.z = (v.z - mu)*rstd*lg4.z + lb4.z;
            o.w = (v.w - mu)*rstd*lg4.w + lb4.w;
            *(float4*)&g_h[(b*NQ + n0 + node)*CQ + 4*lane] = o;
        }
    }
}

// ---------------- K9: regression head ----------------
__global__ void k_reg(const float* __restrict__ reg_w,
                      const float* __restrict__ reg_b,
                      float* __restrict__ out) {
    __shared__ float rw[PQ*256];
    __shared__ float rb[PQ];
    int t = threadIdx.x, b = blockIdx.y;
    for (int i = 0; i < 12; i++) rw[i*256 + t] = reg_w[i*256 + t];
    if (t < PQ) rb[t] = reg_b[t];
    __syncthreads();
    int w = t >> 5, l = t & 31;
    int n = blockIdx.x*8 + w;
    int base = (b*NQ + n)*CQ;
    float4 s4 = *(const float4*)&g_h0[base + 4*l];
    float4 h4 = *(const float4*)&g_h [base + 4*l];
    float acc[PQ];
    #pragma unroll
    for (int p = 0; p < PQ; p++) {
        float4 a = *(const float4*)&rw[p*256 + 4*l];
        float4 c2 = *(const float4*)&rw[p*256 + 128 + 4*l];
        acc[p] = s4.x*a.x + s4.y*a.y + s4.z*a.z + s4.w*a.w
               + h4.x*c2.x + h4.y*c2.y + h4.z*c2.z + h4.w*c2.w;
    }
    #pragma unroll
    for (int p = 0; p < PQ; p++) {
        #pragma unroll
        for (int off = 1; off < 32; off <<= 1)
            acc[p] += __shfl_xor_sync(0xffffffffu, acc[p], off);
    }
    if (l == 0) {
        #pragma unroll
        for (int p = 0; p < PQ; p++)
            out[(b*PQ + p)*NQ + n] = acc[p] + rb[p];
    }
}

// ---------------- driver ----------------
extern "C" void kernel_launch(void* const* d_in, const int* in_sizes, int n_in,
                              void* d_out, int out_size) {
    const float* x        = (const float*)d_in[0];
    const float* x_mark   = (const float*)d_in[1];
    const float* node_emb = (const float*)d_in[2];
    const float* time_tab = (const float*)d_in[3];
    const float* week_tab = (const float*)d_in[4];
    const float* input_w  = (const float*)d_in[5];
    const float* input_b  = (const float*)d_in[6];
    const float* w1_w     = (const float*)d_in[7];
    const float* w1_b     = (const float*)d_in[8];
    const float* w2_w     = (const float*)d_in[9];
    const float* w2_b     = (const float*)d_in[10];
    const float* in_w     = (const float*)d_in[11];
    const float* in_b     = (const float*)d_in[12];
    const float* out_w    = (const float*)d_in[13];
    const float* out_b    = (const float*)d_in[14];
    const float* ln_g     = (const float*)d_in[15];
    const float* ln_b     = (const float*)d_in[16];
    const float* reg_w    = (const float*)d_in[17];
    const float* reg_b    = (const float*)d_in[18];
    const float* proj     = (const float*)d_in[19];
    float* out = (float*)d_out;

    static int attr_done = 0;
    if (!attr_done) {
        cudaFuncSetAttribute(k_gatekv, cudaFuncAttributeMaxDynamicSharedMemorySize, K7_SMEM);
        cudaFuncSetAttribute(k_apply,  cudaFuncAttributeMaxDynamicSharedMemorySize, K8_SMEM);
        attr_done = 1;
    }

    k_prep<<<BQ, 128>>>(x_mark, time_tab, week_tab, input_w, input_b,
                        w1_w, w1_b, w2_w, w2_b);
    k_nodeA<<<NQ/8, 256>>>(node_emb, w1_w, w2_w);
    k_embed<<<dim3((NQ + 255)/256, BQ), 256>>>(x, input_w, node_emb);
    k_phi1<<<dim3(NQ/32, BQ), 256>>>(proj);
    k_phi2<<<dim3(40, BQ), 256>>>();
    k_den<<<dim3(NQ/8, BQ), 256>>>();

    for (int layer = 0; layer < LQ; layer++) {
        k_zero<<<32, 256>>>();
        k_gatekv<<<dim3(18, BQ), 256, K7_SMEM>>>(layer, in_w, in_b, out_w, out_b);
        k_apply<<<dim3(18, BQ), 256, K8_SMEM>>>(layer, ln_g, ln_b);
    }
    k_reg<<<dim3(NQ/8, BQ), 256>>>(reg_w, reg_b, out);
}

// round 14
// speedup vs baseline: 1.0068x; 1.0068x over previous
#include <cuda_runtime.h>
#include <math.h>

#define BQ 8
#define TQ 96
#define NQ 20000
#define PQ 12
#define LQ 3
#define DQ 32
#define CQ 128
#define MQ 64

// ---------------- scratch (static device globals; no allocation) ----------------
__device__ float g_h   [BQ*NQ*CQ];   // evolving hidden state
__device__ float g_h0  [BQ*NQ*CQ];   // skip copy
__device__ float g_phiq[BQ*NQ*MQ];   // phi_q (later scaled by 1/den)
__device__ float g_phik[BQ*NQ*MQ];   // pass1: dash_k - diag_k ; pass2: phi_k
__device__ float g_A1  [NQ*DQ];
__device__ float g_A2  [NQ*DQ];
__device__ float g_kv  [BQ*MQ*CQ];
__device__ float g_ksum[BQ*MQ];
__device__ unsigned int g_kmax[BQ];
__device__ float g_T1[BQ*DQ], g_T2[BQ*DQ], g_bias2[BQ*DQ];
__device__ float g_te[BQ*DQ], g_we[BQ*DQ];

// ---------------- helpers ----------------
union F2U { float2 f; unsigned long long u; };
__device__ __forceinline__ float2 ffma2(float2 a, float2 b, float2 c) {
    F2U A, Bv, Cv, Dv; A.f = a; Bv.f = b; Cv.f = c;
    asm("fma.rn.f32x2 %0, %1, %2, %3;" : "=l"(Dv.u) : "l"(A.u), "l"(Bv.u), "l"(Cv.u));
    return Dv.f;
}
__device__ __forceinline__ float2 fdup(float x) { return make_float2(x, x); }

__device__ __forceinline__ unsigned fkey(float f) {
    unsigned u = __float_as_uint(f);
    return (u & 0x80000000u) ? ~u : (u | 0x80000000u);
}
__device__ __forceinline__ float fdec(unsigned k) {
    unsigned u = (k & 0x80000000u) ? (k ^ 0x80000000u) : ~k;
    return __uint_as_float(u);
}

#define SCALE_RF 0.4204482076268573f   /* 32^(-1/4) */
#define RATIO_RF 0.125f                /* 1/sqrt(64) */
#define EPS_RF   1e-6f
#define IST      2.0f                  /* 1/sqrt(tau), tau=0.25 */

// ---------------- K0: per-batch precompute ----------------
__global__ void k_prep(const float* __restrict__ x_mark,
                       const float* __restrict__ time_tab,
                       const float* __restrict__ week_tab,
                       const float* __restrict__ input_w,
                       const float* __restrict__ input_b,
                       const float* __restrict__ w1_w, const float* __restrict__ w1_b,
                       const float* __restrict__ w2_w, const float* __restrict__ w2_b) {
    int b = blockIdx.x, t = threadIdx.x;
    __shared__ float m0[TQ], m1[TQ];
    __shared__ int s_tod, s_dow;
    if (t < TQ) { m0[t] = x_mark[(b*TQ + t)*2 + 0]; m1[t] = x_mark[(b*TQ + t)*2 + 1]; }
    __syncthreads();
    if (t == 0) {
        int tod = (int)(m0[TQ-1] * (float)TQ); tod = min(max(tod, 0), TQ-1);
        int dow = (int)(m1[TQ-1] * 7.0f);      dow = min(max(dow, 0), 6);
        s_tod = tod; s_dow = dow;
    }
    __syncthreads();
    if (t < DQ) {
        int c = t;
        float a1 = w1_b[c], a2 = w2_b[c];
        #pragma unroll
        for (int g = 0; g < DQ; g++) {
            float te = time_tab[s_tod*DQ + g], we = week_tab[s_dow*DQ + g];
            a1 += te * w1_w[c*96 + 32 + g] + we * w1_w[c*96 + 64 + g];
            a2 += te * w2_w[c*96 + 32 + g] + we * w2_w[c*96 + 64 + g];
        }
        g_T1[b*DQ + c] = IST * a1;
        g_T2[b*DQ + c] = IST * a2;
        float bb = input_b[c];
        for (int tt = 0; tt < TQ; tt++)
            bb += m0[tt] * input_w[c*288 + 96 + tt] + m1[tt] * input_w[c*288 + 192 + tt];
        g_bias2[b*DQ + c] = bb;
        g_te[b*DQ + c] = time_tab[s_tod*DQ + c];
        g_we[b*DQ + c] = week_tab[s_dow*DQ + c];
    }
    if (t < MQ) g_ksum[b*MQ + t] = 0.0f;
    if (t == 0) g_kmax[b] = 0u;
}

// ---------------- K1: A1/A2 node matrices ----------------
__global__ void k_nodeA(const float* __restrict__ node_emb,
                        const float* __restrict__ w1_w,
                        const float* __restrict__ w2_w) {
    __shared__ float w1s[32*33], w2s[32*33], ne[8*33];
    int t = threadIdx.x;
    for (int i = 0; i < 4; i++) {
        int idx = i*256 + t; int c = idx >> 5, g = idx & 31;
        w1s[c*33 + g] = w1_w[c*96 + g];
        w2s[c*33 + g] = w2_w[c*96 + g];
    }
    {
        int row = t >> 5, g = t & 31;
        ne[row*33 + g] = node_emb[(blockIdx.x*8 + row)*DQ + g];
    }
    __syncthreads();
    int row = t >> 5, c = t & 31;
    int n = blockIdx.x*8 + row;
    float a1 = 0.f, a2 = 0.f;
    #pragma unroll
    for (int g = 0; g < 32; g++) {
        float nv = ne[row*33 + g];
        a1 += nv * w1s[c*33 + g];
        a2 += nv * w2s[c*33 + g];
    }
    g_A1[n*DQ + c] = IST * a1;
    g_A2[n*DQ + c] = IST * a2;
}

// ---------------- K2: input embedding + build h/h0 ----------------
__global__ void k_embed(const float* __restrict__ x,
                        const float* __restrict__ input_w,
                        const float* __restrict__ node_emb) {
    __shared__ float ws[TQ*36];
    int t = threadIdx.x, b = blockIdx.y;
    for (int i = 0; i < 12; i++) {
        int idx = i*256 + t;
        if (idx < TQ*DQ) {
            int c = idx / TQ, tt = idx % TQ;
            ws[tt*36 + c] = input_w[c*288 + tt];
        }
    }
    __syncthreads();
    int n = blockIdx.x*256 + t;
    if (n >= NQ) return;
    float acc[32];
    #pragma unroll
    for (int c = 0; c < 32; c++) acc[c] = 0.f;
    for (int tt = 0; tt < TQ; tt++) {
        float xv = x[(b*TQ + tt)*NQ + n];
        const float4* wrow = (const float4*)&ws[tt*36];
        #pragma unroll
        for (int c4 = 0; c4 < 8; c4++) {
            float4 w = wrow[c4];
            acc[4*c4+0] += xv * w.x; acc[4*c4+1] += xv * w.y;
            acc[4*c4+2] += xv * w.z; acc[4*c4+3] += xv * w.w;
        }
    }
    int base = (b*NQ + n)*CQ;
    const float4* b4  = (const float4*)&g_bias2[b*DQ];
    const float4* te4 = (const float4*)&g_te[b*DQ];
    const float4* we4 = (const float4*)&g_we[b*DQ];
    const float4* ne4 = (const float4*)&node_emb[n*DQ];
    #pragma unroll
    for (int c4 = 0; c4 < 8; c4++) {
        float4 bb = b4[c4];
        float4 v = make_float4(acc[4*c4+0]+bb.x, acc[4*c4+1]+bb.y,
                               acc[4*c4+2]+bb.z, acc[4*c4+3]+bb.w);
        ((float4*)&g_h [base])[c4] = v;  ((float4*)&g_h0[base])[c4] = v;
        float4 nv = ne4[c4];
        ((float4*)&g_h [base+32])[c4] = nv; ((float4*)&g_h0[base+32])[c4] = nv;
        float4 tv = te4[c4];
        ((float4*)&g_h [base+64])[c4] = tv; ((float4*)&g_h0[base+64])[c4] = tv;
        float4 wv = we4[c4];
        ((float4*)&g_h [base+96])[c4] = wv; ((float4*)&g_h0[base+96])[c4] = wv;
    }
}

// ---------------- K3: phi pass 1 ----------------
// phi_q finalized (per-row stabilizer); phi_k stored as dash_k - diag_k; per-b max(dash_k) atomically.
__global__ void k_phi1(const float* __restrict__ proj) {
    __shared__ float proj_s[MQ*33];
    __shared__ float nv1_s[32*33], nv2_s[32*33];
    __shared__ float diag1[32], diag2[32];
    __shared__ unsigned s_bmax;
    int t = threadIdx.x, b = blockIdx.y;
    int n0 = blockIdx.x * 32;
    if (t == 0) s_bmax = 0u;
    for (int i = 0; i < 8; i++) {
        int idx = i*256 + t; int m = idx >> 5, d = idx & 31;
        proj_s[m*33 + d] = proj[m*32 + d];
    }
    for (int i = 0; i < 4; i++) {
        int idx = i*256 + t; int r = idx >> 5, d = idx & 31;
        float tv1 = g_T1[b*DQ + d], tv2 = g_T2[b*DQ + d];
        nv1_s[r*33 + d] = g_A1[(n0 + r)*DQ + d] + tv1;
        nv2_s[r*33 + d] = g_A2[(n0 + r)*DQ + d] + tv2;
    }
    __syncthreads();
    if (t < 64) {
        int r = t & 31;
        const float* src = (t < 32) ? &nv1_s[r*33] : &nv2_s[r*33];
        float s = 0.f;
        #pragma unroll
        for (int d = 0; d < 32; d++) { float v = src[d]; s += v*v; }
        float dg = 0.5f * SCALE_RF * SCALE_RF * s;
        if (t < 32) diag1[r] = dg; else diag2[r] = dg;
    }
    __syncthreads();

    int r = t >> 3, j = t & 7;
    int n = n0 + r;
    int base = (b*NQ + n)*MQ;

    // ---- query ----
    {
        float nvr[32];
        #pragma unroll
        for (int d = 0; d < 32; d++) nvr[d] = nv1_s[r*33 + d];
        float dq[8];
        #pragma unroll
        for (int k = 0; k < 8; k++) {
            int m = j + 8*k;
            float s = 0.f;
            #pragma unroll
            for (int d = 0; d < 32; d++) s += nvr[d] * proj_s[m*33 + d];
            dq[k] = s * SCALE_RF;
        }
        float mx = dq[0];
        #pragma unroll
        for (int k = 1; k < 8; k++) mx = fmaxf(mx, dq[k]);
        #pragma unroll
        for (int off = 1; off < 8; off <<= 1)
            mx = fmaxf(mx, __shfl_xor_sync(0xffffffffu, mx, off));
        float dg = diag1[r];
        #pragma unroll
        for (int k = 0; k < 8; k++)
            g_phiq[base + j + 8*k] = RATIO_RF * (__expf(dq[k] - dg - mx) + EPS_RF);
    }
    // ---- key ----
    {
        float nvr[32];
        #pragma unroll
        for (int d = 0; d < 32; d++) nvr[d] = nv2_s[r*33 + d];
        float mxk = -1e30f;
        float dg = diag2[r];
        #pragma unroll
        for (int k = 0; k < 8; k++) {
            int m = j + 8*k;
            float s = 0.f;
            #pragma unroll
            for (int d = 0; d < 32; d++) s += nvr[d] * proj_s[m*33 + d];
            float dk = s * SCALE_RF;
            mxk = fmaxf(mxk, dk);
            g_phik[base + m] = dk - dg;
        }
        #pragma unroll
        for (int off = 1; off < 32; off <<= 1)
            mxk = fmaxf(mxk, __shfl_xor_sync(0xffffffffu, mxk, off));
        if ((t & 31) == 0) atomicMax(&s_bmax, fkey(mxk));
    }
    __syncthreads();
    if (t == 0) atomicMax(&g_kmax[b], s_bmax);
}

// ---------------- K4: phi_k finalize + ksum ----------------
__global__ void k_phi2() {
    __shared__ float red[4][MQ];
    int t = threadIdx.x, b = blockIdx.y;
    int m = t & 63, g = t >> 6;
    float kmaxf = fdec(g_kmax[b]);
    int n0 = blockIdx.x * 500;
    float s = 0.f;
    for (int n = n0 + g; n < n0 + 500; n += 4) {
        int idx = (b*NQ + n)*MQ + m;
        float v = RATIO_RF * (__expf(g_phik[idx] - kmaxf) + EPS_RF);
        g_phik[idx] = v;
        s += v;
    }
    red[g][m] = s;
    __syncthreads();
    if (t < MQ) {
        float tot = red[0][t] + red[1][t] + red[2][t] + red[3][t];
        atomicAdd(&g_ksum[b*MQ + t], tot);
    }
}

// ---------------- K5: fold 1/den into phi_q ----------------
__global__ void k_den() {
    __shared__ float ks[MQ];
    int t = threadIdx.x, b = blockIdx.y;
    if (t < MQ) ks[t] = g_ksum[b*MQ + t];
    __syncthreads();
    int w = t >> 5, l = t & 31;
    int n = blockIdx.x*8 + w;
    int base = (b*NQ + n)*MQ;
    float v0 = g_phiq[base + l], v1 = g_phiq[base + 32 + l];
    float p = v0 * ks[l] + v1 * ks[32 + l];
    #pragma unroll
    for (int off = 1; off < 32; off <<= 1)
        p += __shfl_xor_sync(0xffffffffu, p, off);
    float inv = 1.0f / p;
    g_phiq[base + l] = v0 * inv;
    g_phiq[base + 32 + l] = v1 * inv;
}

// ---------------- K6: zero kv ----------------
__global__ void k_zero() {
    int idx = (blockIdx.x*256 + threadIdx.x) * 8;
    #pragma unroll
    for (int i = 0; i < 8; i++) g_kv[idx + i] = 0.f;
}

// ---------------- K7: fused gate + kv accumulation ----------------
#define K7_SMEM ((2*128*129 + 128*34 + 32*128 + 32*64) * 4)
__global__ __launch_bounds__(256, 1)
void k_gatekv(int layer,
              const float* __restrict__ in_w,  const float* __restrict__ in_b,
              const float* __restrict__ out_w, const float* __restrict__ out_b) {
    extern __shared__ float sm[];
    float* wgIn  = sm;                       // [128][129] : wgIn[g*129+c]
    float* wgOut = wgIn  + 128*129;
    float* hT    = wgOut + 128*129;          // [128][34]  : hT[c*34+n]
    float* uS    = hT    + 128*34;           // [32][128]
    float* phS   = uS    + 32*128;           // [32][64]

    int t = threadIdx.x, b = blockIdx.y;
    // load transposed weights
    for (int i = 0; i < 64; i++) {
        int flat = i*256 + t;
        int c = flat >> 7, g = flat & 127;
        wgIn [g*129 + c] = in_w [(layer*CQ + c)*CQ + g];
        wgOut[g*129 + c] = out_w[(layer*CQ + c)*CQ + g];
    }
    int c  = t & 127, q = t >> 7;           // phase-1 mapping
    int m0 = t & 31,  cg = t >> 5;          // phase-2 mapping
    int c0 = cg * 16;
    float bIn  = in_b [layer*CQ + c];
    float bOut = out_b[layer*CQ + c];

    float2 kvacc[16];
    #pragma unroll
    for (int i = 0; i < 16; i++) kvacc[i] = make_float2(0.f, 0.f);

    int t0 = blockIdx.x * 35;
    int t1 = min(t0 + 35, NQ/32);
    for (int tile = t0; tile < t1; tile++) {
        int n0 = tile * 32;
        __syncthreads();
        // stage h (transposed) and phi_k
        for (int i = 0; i < 16; i++) {
            int flat = i*256 + t; int n = flat >> 7, cc = flat & 127;
            hT[cc*34 + n] = g_h[(b*NQ + n0 + n)*CQ + cc];
        }
        for (int i = 0; i < 8; i++) {
            int flat = i*256 + t; int n = flat >> 6, m = flat & 63;
            phS[n*MQ + m] = g_phik[(b*NQ + n0 + n)*MQ + m];
        }
        __syncthreads();

        // ---- phase 1: gates (node pairs packed f32x2) ----
        float2 ain[8], aout[8];
        #pragma unroll
        for (int p = 0; p < 8; p++) { ain[p] = fdup(bIn); aout[p] = fdup(bOut); }
        #pragma unroll 4
        for (int g = 0; g < 128; g++) {
            float2 wi = fdup(wgIn [g*129 + c]);
            float2 wo = fdup(wgOut[g*129 + c]);
            const float* hrow = &hT[g*34];
            #pragma unroll
            for (int p = 0; p < 8; p++) {
                int pr = q + 2*p;
                float2 h2 = *(const float2*)&hrow[2*pr];
                ain [p] = ffma2(h2, wi, ain [p]);
                aout[p] = ffma2(h2, wo, aout[p]);
            }
        }
        #pragma unroll
        for (int p = 0; p < 8; p++) {
            int pr = q + 2*p;
            float u0 = (1.f / (1.f + __expf(-ain[p].x))) * aout[p].x;
            float u1 = (1.f / (1.f + __expf(-ain[p].y))) * aout[p].y;
            uS[(2*pr  )*CQ + c] = u0;
            uS[(2*pr+1)*CQ + c] = u1;
        }
        __syncthreads();

        // ---- phase 2: kv += phi_k^T u ----
        #pragma unroll 2
        for (int n = 0; n < 32; n++) {
            float2 pa = fdup(phS[n*MQ + m0]);
            float2 pb = fdup(phS[n*MQ + m0 + 32]);
            const float* urow = &uS[n*CQ + c0];
            #pragma unroll
            for (int j = 0; j < 8; j++) {
                float2 u2 = *(const float2*)&urow[2*j];
                kvacc[j]     = ffma2(pa, u2, kvacc[j]);
                kvacc[8 + j] = ffma2(pb, u2, kvacc[8 + j]);
            }
        }
    }
    // flush kv
    #pragma unroll
    for (int j = 0; j < 8; j++) {
        atomicAdd(&g_kv[(b*MQ + m0     )*CQ + c0 + 2*j    ], kvacc[j].x);
        atomicAdd(&g_kv[(b*MQ + m0     )*CQ + c0 + 2*j + 1], kvacc[j].y);
        atomicAdd(&g_kv[(b*MQ + m0 + 32)*CQ + c0 + 2*j    ], kvacc[8+j].x);
        atomicAdd(&g_kv[(b*MQ + m0 + 32)*CQ + c0 + 2*j + 1], kvacc[8+j].y);
    }
}

// ---------------- K8: apply attention + residual + LayerNorm ----------------
#define K8_SMEM ((64*128 + 64*34 + 32*132) * 4)
__global__ __launch_bounds__(256, 1)
void k_apply(int layer,
             const float* __restrict__ ln_g, const float* __restrict__ ln_b) {
    extern __shared__ float sm[];
    float* kv_s = sm;                 // [64][128]
    float* phiT = kv_s + 64*128;      // [64][34] : phiT[m*34+n]
    float* hout = phiT + 64*34;       // [32][132]

    int t = threadIdx.x, b = blockIdx.y;
    for (int i = 0; i < 32; i++) {
        int idx = i*256 + t;
        kv_s[idx] = g_kv[b*MQ*CQ + idx];
    }
    int c = t & 127, q = t >> 7;
    int warpId = t >> 5, lane = t & 31;
    float4 lg4 = *(const float4*)&ln_g[layer*CQ + 4*lane];
    float4 lb4 = *(const float4*)&ln_b[layer*CQ + 4*lane];

    int t0 = blockIdx.x * 35;
    int t1 = min(t0 + 35, NQ/32);
    for (int tile = t0; tile < t1; tile++) {
        int n0 = tile * 32;
        __syncthreads();
        for (int i = 0; i < 8; i++) {
            int flat = i*256 + t; int n = flat >> 6, m = flat & 63;
            phiT[m*34 + n] = g_phiq[(b*NQ + n0 + n)*MQ + m];
        }
        __syncthreads();

        float2 acc[8];
        #pragma unroll
        for (int p = 0; p < 8; p++) acc[p] = make_float2(0.f, 0.f);
        #pragma unroll 4
        for (int m = 0; m < 64; m++) {
            float2 k2 = fdup(kv_s[m*CQ + c]);
            const float* prow = &phiT[m*34];
            #pragma unroll
            for (int p = 0; p < 8; p++) {
                int pr = q + 2*p;
                float2 ph2 = *(const float2*)&prow[2*pr];
                acc[p] = ffma2(ph2, k2, acc[p]);
            }
        }
        #pragma unroll
        for (int p = 0; p < 8; p++) {
            int pr = q + 2*p;
            int na = 2*pr, nb = 2*pr + 1;
            float r0 = g_h[(b*NQ + n0 + na)*CQ + c];
            float r1 = g_h[(b*NQ + n0 + nb)*CQ + c];
            hout[na*132 + c] = acc[p].x + r0;
            hout[nb*132 + c] = acc[p].y + r1;
        }
        __syncthreads();

        // LayerNorm: warp per node
        for (int rep = 0; rep < 4; rep++) {
            int node = rep*8 + warpId;
            float4 v = *(const float4*)&hout[node*132 + 4*lane];
            float s  = v.x + v.y + v.z + v.w;
            float s2 = v.x*v.x + v.y*v.y + v.z*v.z + v.w*v.w;
            #pragma unroll
            for (int off = 1; off < 32; off <<= 1) {
                s  += __shfl_xor_sync(0xffffffffu, s,  off);
                s2 += __shfl_xor_sync(0xffffffffu, s2, off);
            }
            float mu  = s * (1.0f/128.0f);
            float var = s2 * (1.0f/128.0f) - mu*mu;
            float rstd = rsqrtf(var + 1e-5f);
            float4 o;
            o.x = (v.x - mu)*rstd*lg4.x + lb4.x;
            o.y = (v.y - mu)*rstd*lg4.y + lb4.y;
            o.z = (v.z - mu)*rstd*lg4.z + lb4.z;
            o.w = (v.w - mu)*rstd*lg4.w + lb4.w;
            *(float4*)&g_h[(b*NQ + n0 + node)*CQ + 4*lane] = o;
        }
    }
}

// ---------------- K9: regression head ----------------
__global__ void k_reg(const float* __restrict__ reg_w,
                      const float* __restrict__ reg_b,
                      float* __restrict__ out) {
    __shared__ float rw[PQ*256];
    __shared__ float rb[PQ];
    int t = threadIdx.x, b = blockIdx.y;
    for (int i = 0; i < 12; i++) rw[i*256 + t] = reg_w[i*256 + t];
    if (t < PQ) rb[t] = reg_b[t];
    __syncthreads();
    int w = t >> 5, l = t & 31;
    int n = blockIdx.x*8 + w;
    int base = (b*NQ + n)*CQ;
    float4 s4 = *(const float4*)&g_h0[base + 4*l];
    float4 h4 = *(const float4*)&g_h [base + 4*l];
    float acc[PQ];
    #pragma unroll
    for (int p = 0; p < PQ; p++) {
        float4 a = *(const float4*)&rw[p*256 + 4*l];
        float4 c2 = *(const float4*)&rw[p*256 + 128 + 4*l];
        acc[p] = s4.x*a.x + s4.y*a.y + s4.z*a.z + s4.w*a.w
               + h4.x*c2.x + h4.y*c2.y + h4.z*c2.z + h4.w*c2.w;
    }
    #pragma unroll
    for (int p = 0; p < PQ; p++) {
        #pragma unroll
        for (int off = 1; off < 32; off <<= 1)
            acc[p] += __shfl_xor_sync(0xffffffffu, acc[p], off);
    }
    if (l == 0) {
        #pragma unroll
        for (int p = 0; p < PQ; p++)
            out[(b*PQ + p)*NQ + n] = acc[p] + rb[p];
    }
}

// ---------------- driver ----------------
extern "C" void kernel_launch(void* const* d_in, const int* in_sizes, int n_in,
                              void* d_out, int out_size) {
    const float* x        = (const float*)d_in[0];
    const float* x_mark   = (const float*)d_in[1];
    const float* node_emb = (const float*)d_in[2];
    const float* time_tab = (const float*)d_in[3];
    const float* week_tab = (const float*)d_in[4];
    const float* input_w  = (const float*)d_in[5];
    const float* input_b  = (const float*)d_in[6];
    const float* w1_w     = (const float*)d_in[7];
    const float* w1_b     = (const float*)d_in[8];
    const float* w2_w     = (const float*)d_in[9];
    const float* w2_b     = (const float*)d_in[10];
    const float* in_w     = (const float*)d_in[11];
    const float* in_b     = (const float*)d_in[12];
    const float* out_w    = (const float*)d_in[13];
    const float* out_b    = (const float*)d_in[14];
    const float* ln_g     = (const float*)d_in[15];
    const float* ln_b     = (const float*)d_in[16];
    const float* reg_w    = (const float*)d_in[17];
    const float* reg_b    = (const float*)d_in[18];
    const float* proj     = (const float*)d_in[19];
    float* out = (float*)d_out;

    static int attr_done = 0;
    if (!attr_done) {
        cudaFuncSetAttribute(k_gatekv, cudaFuncAttributeMaxDynamicSharedMemorySize, K7_SMEM);
        cudaFuncSetAttribute(k_apply,  cudaFuncAttributeMaxDynamicSharedMemorySize, K8_SMEM);
        attr_done = 1;
    }

    k_prep<<<BQ, 128>>>(x_mark, time_tab, week_tab, input_w, input_b,
                        w1_w, w1_b, w2_w, w2_b);
    k_nodeA<<<NQ/8, 256>>>(node_emb, w1_w, w2_w);
    k_embed<<<dim3((NQ + 255)/256, BQ), 256>>>(x, input_w, node_emb);
    k_phi1<<<dim3(NQ/32, BQ), 256>>>(proj);
    k_phi2<<<dim3(40, BQ), 256>>>();
    k_den<<<dim3(NQ/8, BQ), 256>>>();

    for (int layer = 0; layer < LQ; layer++) {
        k_zero<<<32, 256>>>();
        k_gatekv<<<dim3(18, BQ), 256, K7_SMEM>>>(layer, in_w, in_b, out_w, out_b);
        k_apply<<<dim3(18, BQ), 256, K8_SMEM>>>(layer, ln_g, ln_b);
    }
    k_reg<<<dim3(NQ/8, BQ), 256>>>(reg_w, reg_b, out);
}